// round 9
// baseline (speedup 1.0000x reference)
#include <cuda_runtime.h>

// Problem constants
#define TT 1024   // T: tickers / states
#define MM 8      // M: mesa rank
#define NN 32768  // N: samples
#define DD 32     // D: input dim
#define HH 64     // H: hidden dim
#define SS 2177   // S = H*D + H + O*H + O
#define SP 2192   // padded state row stride (float4-aligned)
#define CAP 128   // bucket capacity per ticker

#define STATE_BLOCKS 288   // 32 t-tiles x 9 dst-tiles
#define SCAT_BLOCKS  32    // 32768 / (4 * 256)
#define NSPLIT 4           // h-slices per ticker (independent warps)

// Scratch (__device__ globals; zero-initialized at load).
// d_count is zeroed by k_combine each run (NOT by k_compute: 4 independent
// warps read each counter, a read-and-reset would race).
__device__ int   d_count[TT];
__device__ int   d_bucket[TT * CAP];
__device__ float d_states[TT * SP];        // rows in PERMUTED (j*64+h) order
__device__ float d_part[NSPLIT * NN];      // per-slice partial outputs

__device__ __forceinline__ unsigned long long fma2(
    unsigned long long a, unsigned long long b, unsigned long long c) {
    unsigned long long d;
    asm("fma.rn.f32x2 %0, %1, %2, %3;" : "=l"(d) : "l"(a), "l"(b), "l"(c));
    return d;
}
__device__ __forceinline__ unsigned long long dup2(float v) {
    unsigned long long d;
    asm("mov.b64 %0, {%1, %1};" : "=l"(d) : "f"(v));
    return d;
}

// ---------------------------------------------------------------------------
// k_prep: blocks [0,288) build effective states in PERMUTED layout:
//   row[d], d = j*64 + h  holds  w1_eff[h][j]   (d < 2048)
//   row[d] = state[d] for d in [2048, 2177)  (b1 | w2 | b2)
// blocks [288,320): bucket-scatter samples by ticker.
// ---------------------------------------------------------------------------
__global__ __launch_bounds__(256) void k_prep(
    const int*   __restrict__ ticker,
    const float* __restrict__ mesa,   // (M, T)
    const float* __restrict__ meta,   // (S, M)
    const float* __restrict__ bias,   // (S,)
    const float* __restrict__ base)   // (S,)
{
    int b   = blockIdx.x;
    int tid = threadIdx.x;

    if (b < STATE_BLOCKS) {
        __shared__ float4 sc4[32][2];     // mesa coeffs for 32 tickers
        int tt = b / 9, st = b % 9;
        int t0 = tt * 32;
        {
            int m = tid >> 5, i = tid & 31;
            ((float*)sc4)[i * 8 + m] = mesa[m * TT + t0 + i];
        }
        __syncthreads();

        int d = st * 256 + tid;           // destination index in permuted row
        int s;
        bool ok = true;
        if (d < 2048) {                   // w1: d = j*64 + h  <->  s = h*32 + j
            int h = d & 63, j = d >> 6;
            s = h * 32 + j;
        } else {
            s = d;
            ok = (d < SS);
        }
        if (ok) {
            const float4* m4 = (const float4*)(meta + s * MM);
            float4 a = m4[0], bq = m4[1];
            float bb = base[s] + bias[s];
#pragma unroll
            for (int i = 0; i < 32; i++) {
                float4 c0 = sc4[i][0];
                float4 c1 = sc4[i][1];
                float v = bb
                    + c0.x * a.x + c0.y * a.y + c0.z * a.z + c0.w * a.w
                    + c1.x * bq.x + c1.y * bq.y + c1.z * bq.z + c1.w * bq.w;
                d_states[(t0 + i) * SP + d] = v;   // coalesced over d
            }
        }
    } else {
        int idx = (b - STATE_BLOCKS) * 256 + tid;
        int4 v = ((const int4*)ticker)[idx];
        int n0 = idx * 4;
        int p;
        p = atomicAdd(&d_count[v.x], 1); if (p < CAP) d_bucket[v.x * CAP + p] = n0;
        p = atomicAdd(&d_count[v.y], 1); if (p < CAP) d_bucket[v.y * CAP + p] = n0 + 1;
        p = atomicAdd(&d_count[v.z], 1); if (p < CAP) d_bucket[v.z * CAP + p] = n0 + 2;
        p = atomicAdd(&d_count[v.w], 1); if (p < CAP) d_bucket[v.w * CAP + p] = n0 + 3;
    }
}

// ---------------------------------------------------------------------------
// k_compute: grid = TT*NSPLIT single-warp blocks, FULLY INDEPENDENT.
// Block b -> ticker t = b>>2, h-slice w = b&3 (h in [16w, 16w+16)).
// Sample-per-lane; 8 f32x2 accumulators per lane (acc[p] = hidden pair
// (h0+2p, h0+2p+1)). Partial output -> d_part[w][n]; b2 folded into w==0.
// ---------------------------------------------------------------------------
__global__ __launch_bounds__(32) void k_compute(
    const float* __restrict__ x)
{
    __shared__ __align__(16) float s_ws[32 * 16];  // slice weights [j][hh]
    __shared__ __align__(16) float s_x[32 * 36];   // staged x, stride 36
    __shared__ __align__(8)  float s_b1[16];
    __shared__ float s_w2[16];
    __shared__ int   s_n[32];

    int b    = blockIdx.x;
    int t    = b >> 2;
    int w    = b & 3;
    int h0   = w * 16;
    int lane = threadIdx.x;

    const float*  rowf = d_states + (size_t)t * SP;
    const float4* row4 = (const float4*)rowf;

    // Slice weight copy: 128 float4 (j = i>>2, q = i&3) -> s_ws[j*16 + q*4 ..]
    float4* s_ws4 = (float4*)s_ws;
#pragma unroll
    for (int it = 0; it < 4; it++) {
        int i = it * 32 + lane;
        int j = i >> 2, q = i & 3;
        s_ws4[i] = row4[j * 16 + w * 4 + q];
    }
    // b1 / w2 slices
    if (lane < 16) s_b1[lane] = rowf[2048 + h0 + lane];
    else           s_w2[lane - 16] = rowf[2112 + h0 + (lane - 16)];
    float b2 = (w == 0) ? rowf[2176] : 0.f;

    int cnt = 0;
    if (lane == 0) cnt = d_count[t];          // NO reset (4 readers/ticker)
    cnt = __shfl_sync(0xffffffffu, cnt, 0);
    if (cnt > CAP) cnt = CAP;
    __syncwarp();
    if (cnt == 0) return;

    const unsigned long long* b1p = (const unsigned long long*)s_b1;

    for (int base = 0; base < cnt; base += 32) {
        int idx = base + lane;
        bool valid = idx < cnt;
        int n = d_bucket[t * CAP + (valid ? idx : cnt - 1)];

        __syncwarp();                 // prior group done with s_n/s_x
        s_n[lane] = n;
        __syncwarp();
#pragma unroll
        for (int k = 0; k < 32; k++) {
            int nk = s_n[k];                          // broadcast LDS
            s_x[k * 36 + lane] = x[nk * DD + lane];   // coalesced 128B rows
        }
        __syncwarp();

        unsigned long long acc[8];
#pragma unroll
        for (int q = 0; q < 8; q++) acc[q] = b1p[q];

        const float4* myx = (const float4*)(s_x + lane * 36);
#pragma unroll
        for (int jq = 0; jq < 8; jq++) {
            float4 xq = myx[jq];                      // own-row LDS.128
            float xe[4] = {xq.x, xq.y, xq.z, xq.w};
#pragma unroll
            for (int e = 0; e < 4; e++) {
                int j = jq * 4 + e;
                unsigned long long xd = dup2(xe[e]);
                const ulonglong2* wr = (const ulonglong2*)(s_ws + j * 16);
#pragma unroll
                for (int q2 = 0; q2 < 4; q2++) {
                    ulonglong2 wv = wr[q2];           // broadcast LDS.128
                    acc[2 * q2]     = fma2(wv.x, xd, acc[2 * q2]);
                    acc[2 * q2 + 1] = fma2(wv.y, xd, acc[2 * q2 + 1]);
                }
            }
        }

        float o = b2;
#pragma unroll
        for (int p = 0; p < 8; p++) {
            float lo = __uint_as_float((unsigned)(acc[p] & 0xffffffffu));
            float hi = __uint_as_float((unsigned)(acc[p] >> 32));
            o += fmaxf(lo, 0.f) * s_w2[2 * p]
               + fmaxf(hi, 0.f) * s_w2[2 * p + 1];
        }
        if (valid) d_part[w * NN + n] = o;
    }
}

// ---------------------------------------------------------------------------
// k_combine: out[n] = sum of 4 slice partials; also zeroes d_count for the
// next replay (runs after compute each iteration, so the invariant
// "d_count == 0 at k_prep entry" holds on every graph replay).
// ---------------------------------------------------------------------------
__global__ __launch_bounds__(256) void k_combine(float* __restrict__ out) {
    int n = blockIdx.x * 256 + threadIdx.x;
    out[n] = d_part[n] + d_part[NN + n] + d_part[2 * NN + n] + d_part[3 * NN + n];
    if (n < TT) d_count[n] = 0;
}

extern "C" void kernel_launch(void* const* d_in, const int* in_sizes, int n_in,
                              void* d_out, int out_size) {
    const float* x    = (const float*)d_in[0];
    const int*   tick = (const int*)d_in[1];
    const float* mesa = (const float*)d_in[2];   // (M, T)
    const float* meta = (const float*)d_in[3];   // (S, M)
    const float* bias = (const float*)d_in[4];   // (S,)
    const float* base = (const float*)d_in[5];   // (S,)
    float* out = (float*)d_out;                  // (N, 1) float32

    k_prep<<<STATE_BLOCKS + SCAT_BLOCKS, 256>>>(tick, mesa, meta, bias, base);
    k_compute<<<TT * NSPLIT, 32>>>(x);
    k_combine<<<NN / 256, 256>>>(out);
}

// round 10
// speedup vs baseline: 1.1836x; 1.1836x over previous
#include <cuda_runtime.h>

// Problem constants
#define TT 1024   // T: tickers / states
#define MM 8      // M: mesa rank
#define NN 32768  // N: samples
#define DD 32     // D: input dim
#define HH 64     // H: hidden dim
#define SS 2177   // S = H*D + H + O*H + O
#define SP 2192   // padded state row stride (float4-aligned)
#define CAP 128   // bucket capacity per ticker

#define STATE_BLOCKS 1152  // 128 t-tiles (8 tickers) x 9 dst-tiles
#define SCAT_BLOCKS  32    // 32768 / (4 * 256)

// Scratch (__device__ globals; d_count zero-init at load, reset by k_compute)
__device__ int   d_count[TT];
__device__ int   d_bucket[TT * CAP];
__device__ float d_states[TT * SP];   // rows stored in PERMUTED (wint) order

__device__ __forceinline__ unsigned long long fma2(
    unsigned long long a, unsigned long long b, unsigned long long c) {
    unsigned long long d;
    asm("fma.rn.f32x2 %0, %1, %2, %3;" : "=l"(d) : "l"(a), "l"(b), "l"(c));
    return d;
}

// ---------------------------------------------------------------------------
// k_prep: blocks [0,1152) build effective states in PERMUTED layout:
//   row[d], d = j*64 + h  holds  w1_eff[h][j]   (d < 2048)
//   row[d] = state[d] for d in [2048, 2177)  (b1 | w2 | b2)
// Tile = 8 tickers x 256 d-positions (4x the blocks of the old 32-ticker
// tile -> ~9.5K warps, occupancy-limited no more; serial per-thread chain
// cut from 32 to 8 iterations).
// blocks [1152,1184): bucket-scatter samples by ticker.
// ---------------------------------------------------------------------------
__global__ __launch_bounds__(256) void k_prep(
    const int*   __restrict__ ticker,
    const float* __restrict__ mesa,   // (M, T)
    const float* __restrict__ meta,   // (S, M)
    const float* __restrict__ bias,   // (S,)
    const float* __restrict__ base)   // (S,)
{
    int b   = blockIdx.x;
    int tid = threadIdx.x;

    if (b < STATE_BLOCKS) {
        __shared__ float4 sc4[8][2];      // mesa coeffs for 8 tickers
        int tt = b / 9, st = b % 9;
        int t0 = tt * 8;
        if (tid < 64) {
            int m = tid >> 3, i = tid & 7;
            ((float*)sc4)[i * 8 + m] = mesa[m * TT + t0 + i];
        }
        __syncthreads();

        int d = st * 256 + tid;           // destination index in permuted row
        int s;
        bool ok = true;
        if (d < 2048) {                   // w1: d = j*64 + h  <->  s = h*32 + j
            int h = d & 63, j = d >> 6;
            s = h * 32 + j;
        } else {
            s = d;
            ok = (d < SS);
        }
        if (ok) {
            const float4* m4 = (const float4*)(meta + s * MM);
            float4 a = m4[0], bq = m4[1];
            float bb = base[s] + bias[s];
#pragma unroll
            for (int i = 0; i < 8; i++) {
                float4 c0 = sc4[i][0];    // broadcast LDS.128
                float4 c1 = sc4[i][1];
                float v = bb
                    + c0.x * a.x + c0.y * a.y + c0.z * a.z + c0.w * a.w
                    + c1.x * bq.x + c1.y * bq.y + c1.z * bq.z + c1.w * bq.w;
                d_states[(t0 + i) * SP + d] = v;   // coalesced over d
            }
        }
    } else {
        int idx = (b - STATE_BLOCKS) * 256 + tid;
        int4 v = ((const int4*)ticker)[idx];
        int n0 = idx * 4;
        int p;
        p = atomicAdd(&d_count[v.x], 1); if (p < CAP) d_bucket[v.x * CAP + p] = n0;
        p = atomicAdd(&d_count[v.y], 1); if (p < CAP) d_bucket[v.y * CAP + p] = n0 + 1;
        p = atomicAdd(&d_count[v.z], 1); if (p < CAP) d_bucket[v.z * CAP + p] = n0 + 2;
        p = atomicAdd(&d_count[v.w], 1); if (p < CAP) d_bucket[v.w * CAP + p] = n0 + 3;
    }
}

// ---------------------------------------------------------------------------
// k_compute: EXACT R5 structure (best measured: 20.8us wall).
// One WARP per ticker (grid=1024, block=32), sample-per-lane, hidden units
// paired in 32 f32x2 accumulators, scalar stride-33 x reads (conflict-free).
// smem floats: [0,2048) wint (j*64+h), [2048,2112) b1, [2112,2176) w2, 2176 b2.
// ---------------------------------------------------------------------------
__global__ __launch_bounds__(32) void k_compute(
    const float* __restrict__ x,
    float* __restrict__ out)
{
    __shared__ __align__(16) float s_w[2180];
    __shared__ float s_x[32 * 33];        // staged x, stride 33 (conflict-free)

    int t    = blockIdx.x;
    int lane = threadIdx.x;

    // Coalesced copy of the permuted state row (545 float4 -> 18 iterations).
    const float4* row4 = (const float4*)(d_states + (size_t)t * SP);
    float4* s_w4 = (float4*)s_w;
#pragma unroll
    for (int i = 0; i < 18; i++) {
        int idx = lane + i * 32;
        if (idx < 545) s_w4[idx] = row4[idx];
    }

    int cnt = 0;
    if (lane == 0) { cnt = d_count[t]; d_count[t] = 0; }
    cnt = __shfl_sync(0xffffffffu, cnt, 0);
    if (cnt > CAP) cnt = CAP;
    __syncwarp();
    if (cnt == 0) return;

    const unsigned long long* b1p =
        (const unsigned long long*)(s_w + 2048);     // b1 as f32x2 pairs
    float b2 = s_w[2176];

    for (int base = 0; base < cnt; base += 32) {
        int idx = base + lane;
        bool valid = idx < cnt;
        int n = d_bucket[t * CAP + (valid ? idx : cnt - 1)];

        __syncwarp();   // previous pass finished reading s_x
#pragma unroll
        for (int k = 0; k < 32; k++) {
            int nk = __shfl_sync(0xffffffffu, n, k);
            s_x[k * 33 + lane] = x[nk * DD + lane];   // coalesced 128B rows
        }
        __syncwarp();

        unsigned long long acc[32];
#pragma unroll
        for (int hp = 0; hp < 32; hp++) acc[hp] = b1p[hp];

#pragma unroll 8
        for (int j = 0; j < 32; j++) {
            float xj = s_x[lane * 33 + j];            // scalar LDS, bank (l+j)
            unsigned long long xd;
            asm("mov.b64 %0, {%1, %1};" : "=l"(xd) : "f"(xj));
            const ulonglong2* wr = (const ulonglong2*)(s_w + j * 64);
#pragma unroll
            for (int hq = 0; hq < 16; hq++) {
                ulonglong2 w = wr[hq];                // broadcast LDS.128
                acc[2 * hq]     = fma2(w.x, xd, acc[2 * hq]);
                acc[2 * hq + 1] = fma2(w.y, xd, acc[2 * hq + 1]);
            }
        }

        float o = b2;
#pragma unroll
        for (int hp = 0; hp < 32; hp++) {
            float lo = __uint_as_float((unsigned)(acc[hp] & 0xffffffffu));
            float hi = __uint_as_float((unsigned)(acc[hp] >> 32));
            o += fmaxf(lo, 0.f) * s_w[2112 + 2 * hp]
               + fmaxf(hi, 0.f) * s_w[2112 + 2 * hp + 1];
        }
        if (valid) out[n] = o;
    }
}

extern "C" void kernel_launch(void* const* d_in, const int* in_sizes, int n_in,
                              void* d_out, int out_size) {
    const float* x    = (const float*)d_in[0];
    const int*   tick = (const int*)d_in[1];
    const float* mesa = (const float*)d_in[2];   // (M, T)
    const float* meta = (const float*)d_in[3];   // (S, M)
    const float* bias = (const float*)d_in[4];   // (S,)
    const float* base = (const float*)d_in[5];   // (S,)
    float* out = (float*)d_out;                  // (N, 1) float32

    k_prep<<<STATE_BLOCKS + SCAT_BLOCKS, 256>>>(tick, mesa, meta, bias, base);
    k_compute<<<TT, 32>>>(x, out);
}